// round 5
// baseline (speedup 1.0000x reference)
#include <cuda_runtime.h>
#include <cstdint>

// Problem constants
#define NUM_PROPERTIES 10000
#define HDIM 512
#define ODIM 2
#define BATCH 512
#define NUM_PROPS 128
#define NROWS (BATCH * NUM_PROPS)   // 65536 (b,p) rows

#define NSM 148
#define CTAS_PER_SM 8
#define GRID_CTAS (NSM * CTAS_PER_SM)          // 1184
#define WARPS_PER_CTA 8
#define TOTAL_WARPS (GRID_CTAS * WARPS_PER_CTA) // 9472

__device__ __forceinline__ float2 ldcs_f2(const float2* p) {
    float2 v;
    asm volatile("ld.global.cs.v2.f32 {%0,%1}, [%2];"
                 : "=f"(v.x), "=f"(v.y) : "l"(p));
    return v;
}

// Persistent grid-stride kernel; one warp per (b,p) row per iteration.
//
// Dtype self-detection (properties may be int32 or int64 depending on JAX
// x64 config): every warp reads p64[lane] (first 256 bytes, in-bounds under
// both interpretations) and ballots whether all 32 values lie in
// [0, NUM_PROPERTIES). int32 data passing this requires 32 consecutive
// odd-index props to be zero (~1e-128). Deterministic and identical across
// warps; window is L1/L2-hot after the first warp.
//
// Software pipeline (R5): the next row's property index is prefetched at the
// top of each iteration so the scalar prop load -> W-address chain (~250-577
// cyc) overlaps the current row's loads/FMAs/reduction instead of
// serializing at each row boundary. mask/bias loads are hoisted to the top
// of the body for the same reason.
//
// Memory layout per row (wavefront-minimal, see R3):
//   W row = 256 float4; lane handles j = lane + 32k, k = 0..7 (contiguous
//   warp-wide); h row = 256 float2 paired 1:1 with W float4s.
// hidden_states + out use evict-first (.cs) so the 40 MiB W table stays in L2.
__global__ __launch_bounds__(256, CTAS_PER_SM)
void adapter_gemv_kernel(
    const float*  __restrict__ hs,     // (B, P, H)
    const int*    __restrict__ props,  // (B, P) int32 or int64 (detected)
    const float*  __restrict__ mask,   // (B, P)
    const float*  __restrict__ W,      // (NUM_PROPERTIES, H, 2)
    const float*  __restrict__ bias,   // (NUM_PROPERTIES, 2)
    float*        __restrict__ out)    // (B, P, 2)
{
    const int lane   = threadIdx.x & 31;
    const int gwarp0 = (blockIdx.x * blockDim.x + threadIdx.x) >> 5;

    // --- per-warp dtype detection (one broadcast 256B window) ---
    const long long* p64 = (const long long*)props;
    long long probe = p64[lane];
    bool in_range = (probe >= 0) && (probe < NUM_PROPERTIES);
    const bool is64 = (__ballot_sync(0xffffffffu, in_range) == 0xffffffffu);

    int row = gwarp0;
    long long prop = is64 ? p64[row] : (long long)props[row];

    while (row < NROWS) {
        // Prefetch next row's property index (hides the prop->W addr chain).
        const int nrow = row + TOTAL_WARPS;
        long long nprop = 0;
        if (nrow < NROWS)
            nprop = is64 ? p64[nrow] : (long long)props[nrow];

        // Hoist epilogue scalars: in flight during the data loads + FMAs.
        float m = 0.0f, b0 = 0.0f, b1 = 0.0f;
        if (lane == 0) {
            m  = mask[row];
            b0 = bias[prop * 2 + 0];
            b1 = bias[prop * 2 + 1];
        }

        const float2* __restrict__ h2 = (const float2*)(hs + (size_t)row * HDIM);
        const float4* __restrict__ w4 = (const float4*)(W + (size_t)prop * (HDIM * ODIM));

        float acc0 = 0.0f, acc1 = 0.0f;
        #pragma unroll 4
        for (int k = 0; k < 8; k++) {
            const int j = lane + 32 * k;
            const float2 h = ldcs_f2(&h2[j]);   // streaming: evict-first
            const float4 w = w4[j];             // default: keep in L2
            acc0 = fmaf(h.x, w.x, acc0);
            acc1 = fmaf(h.x, w.y, acc1);
            acc0 = fmaf(h.y, w.z, acc0);
            acc1 = fmaf(h.y, w.w, acc1);
        }

        #pragma unroll
        for (int off = 16; off > 0; off >>= 1) {
            acc0 += __shfl_xor_sync(0xffffffff, acc0, off);
            acc1 += __shfl_xor_sync(0xffffffff, acc1, off);
        }

        if (lane == 0) {
            float2 r;
            r.x = (acc0 + b0) * m;
            r.y = (acc1 + b1) * m;
            asm volatile("st.global.cs.v2.f32 [%0], {%1,%2};"
                         :: "l"(((float2*)out) + row), "f"(r.x), "f"(r.y));
        }

        row  = nrow;
        prop = nprop;
    }
}

extern "C" void kernel_launch(void* const* d_in, const int* in_sizes, int n_in,
                              void* d_out, int out_size) {
    const float* hs    = (const float*)d_in[0];   // hidden_states (512,128,512) f32
    const int*   props = (const int*)d_in[1];     // properties (512,128)
    const float* mask  = (const float*)d_in[2];   // mask (512,128) f32
    const float* W     = (const float*)d_in[3];   // classifier_weights (10000,512,2) f32
    const float* bias  = (const float*)d_in[4];   // classifier_bias (10000,2) f32
    float*       out   = (float*)d_out;           // (512,128,2) f32

    adapter_gemv_kernel<<<GRID_CTAS, 256>>>(hs, props, mask, W, bias, out);
}